// round 15
// baseline (speedup 1.0000x reference)
#include <cuda_runtime.h>
#include <cuda_fp16.h>
#include <cstdint>

#define SEQ   2048
#define HD    64
#define BATCH 16

// ---------------------------------------------------------------------------
// device scratch
// ---------------------------------------------------------------------------
__device__ __half    g_qh[BATCH * SEQ * HD];        // fp16(q / 8)
__device__ __half    g_kh[BATCH * SEQ * HD];        // fp16(k)
__device__ __half    g_vh[BATCH * HD * SEQ];        // transposed [b][d][t], fp16
__device__ uint32_t  g_maskbits[SEQ * (SEQ / 32)];

#define LOG2E 1.4426950408889634f

// ---------------------------------------------------------------------------
// helpers
// ---------------------------------------------------------------------------
__device__ __forceinline__ uint32_t smem_u32(const void* p) {
    uint32_t a;
    asm("{ .reg .u64 t; cvta.to.shared.u64 t, %1; cvt.u32.u64 %0, t; }" : "=r"(a) : "l"(p));
    return a;
}
__device__ __forceinline__ uint32_t hpack(float a, float b) {
    uint32_t r;
    asm("cvt.rn.f16x2.f32 %0, %1, %2;" : "=r"(r) : "f"(b), "f"(a));
    return r;
}
__device__ __forceinline__ float ex2f(float x) {
    float r;
    asm("ex2.approx.ftz.f32 %0, %1;" : "=f"(r) : "f"(x));
    return r;
}
__device__ __forceinline__ void ldsm_x4(uint32_t& r0, uint32_t& r1, uint32_t& r2,
                                        uint32_t& r3, uint32_t addr) {
    asm volatile("ldmatrix.sync.aligned.m8n8.x4.shared.b16 {%0,%1,%2,%3}, [%4];"
                 : "=r"(r0), "=r"(r1), "=r"(r2), "=r"(r3) : "r"(addr));
}
__device__ __forceinline__ void mma16816h(float* c, const uint32_t* a, const uint32_t* b) {
    asm volatile("mma.sync.aligned.m16n8k16.row.col.f32.f16.f16.f32 "
                 "{%0,%1,%2,%3}, {%4,%5,%6,%7}, {%8,%9}, {%0,%1,%2,%3};"
                 : "+f"(c[0]), "+f"(c[1]), "+f"(c[2]), "+f"(c[3])
                 : "r"(a[0]), "r"(a[1]), "r"(a[2]), "r"(a[3]), "r"(b[0]), "r"(b[1]));
}
#define CP_ASYNC16(dst, src) \
    asm volatile("cp.async.cg.shared.global [%0], [%1], 16;" :: "r"(dst), "l"(src))
#define CP_COMMIT()  asm volatile("cp.async.commit_group;" ::: "memory")
#define CP_WAIT(n)   asm volatile("cp.async.wait_group %0;" :: "n"(n) : "memory")
#define PAIR_BAR(id) asm volatile("bar.sync %0, 64;" :: "r"(id) : "memory")

// ===========================================================================
// fused prep: y=0 mask pack | y=1 q/8, k fp16 convert | y=2 v transpose fp16
// ===========================================================================
__global__ void __launch_bounds__(256) prep_kernel(
    const float4* __restrict__ q, const float4* __restrict__ k,
    const float* __restrict__ v, const int* __restrict__ mask)
{
    __shared__ float sm[64][129];            // used only by y == 2
    const int tid = threadIdx.x;

    if (blockIdx.y == 0) {
        const int gw = (blockIdx.x * 256 + tid) >> 5;
        const int l  = tid & 31;
        const int nwarps = gridDim.x * 8;
        const int ngroups = SEQ * (SEQ / 32) / 4;      // 32768
        for (int g = gw; g < ngroups; g += nwarps) {
            int4 mv = *(const int4*)(mask + (size_t)128 * g + 4 * l);
            uint32_t nib = (uint32_t)(mv.x != 0) | ((uint32_t)(mv.y != 0) << 1) |
                           ((uint32_t)(mv.z != 0) << 2) | ((uint32_t)(mv.w != 0) << 3);
            uint32_t bits = nib << (4 * (l & 7));
            bits |= __shfl_xor_sync(~0u, bits, 1);
            bits |= __shfl_xor_sync(~0u, bits, 2);
            bits |= __shfl_xor_sync(~0u, bits, 4);
            if ((l & 7) == 0) g_maskbits[4 * g + (l >> 3)] = bits;
        }
    } else if (blockIdx.y == 1) {
        const int isK = blockIdx.x >= 256;
        const float4* src = isK ? k : q;
        uint2* hi = (uint2*)(isK ? g_kh : g_qh);
        const float scale = isK ? 1.0f : 0.125f;
        const int n = BATCH * SEQ * HD / 4;
        const int stride = 256 * 256;
        for (int c = (blockIdx.x & 255) * 256 + tid; c < n; c += stride) {
            float4 x = src[c];
            hi[c] = make_uint2(hpack(x.x * scale, x.y * scale),
                               hpack(x.z * scale, x.w * scale));
        }
    } else {
        if (blockIdx.x >= 256) return;
        const int b = blockIdx.x >> 4, t0 = (blockIdx.x & 15) * 128;
        const float* vb = v + (size_t)b * SEQ * HD;
#pragma unroll
        for (int i = 0; i < 8; ++i) {
            int chunk = tid + i * 256;
            int t = chunk >> 4, d4 = (chunk & 15) * 4;
            float4 x = *(const float4*)(vb + (size_t)(t0 + t) * HD + d4);
            sm[d4 + 0][t] = x.x; sm[d4 + 1][t] = x.y;
            sm[d4 + 2][t] = x.z; sm[d4 + 3][t] = x.w;
        }
        __syncthreads();
        const int r = tid >> 2, tb = (tid & 3) * 32;
        size_t obase = ((size_t)(b * 64 + r)) * SEQ + t0 + tb;
#pragma unroll
        for (int seg = 0; seg < 4; ++seg) {
            uint32_t h[4];
#pragma unroll
            for (int j = 0; j < 4; ++j)
                h[j] = hpack(sm[r][tb + seg * 8 + j * 2],
                             sm[r][tb + seg * 8 + j * 2 + 1]);
            *(uint4*)(g_vh + obase + seg * 8) = make_uint4(h[0], h[1], h[2], h[3]);
        }
    }
}

// ===========================================================================
// fused attention: one CTA = 64 rows. 64-iteration mainloop:
//   it 0..31  (pass 1): QK mma on streamed k-tiles, exp, row-sum accumulate
//   boundary: reduce sums -> sinv (smem)
//   it 32..63 (pass 2): QK mma again (k L2-hot) + epilogue (p = e*inv ->
//                       fp32 attn + fp16 AP) + PV mma (out += p @ v)
// smem: QT 8K | KT 2x8K | VT 2x8K | AP 8K | SINV 256 | SSUM 512
// ===========================================================================
__global__ void __launch_bounds__(256, 2) attn_fused_kernel(
    float* __restrict__ attn, float* __restrict__ out)
{
    extern __shared__ char smem[];
    constexpr int QT = 0, KT = 8192, VT = 24576, AP = 40960,
                  SINV = 49152, SSUM = 49408;
    const uint32_t sb = smem_u32(smem);
    const int tid = threadIdx.x, wid = tid >> 5, l = tid & 31;
    const int b = blockIdx.y, row0 = blockIdx.x * 64;

    const __half* qrow  = g_qh + ((size_t)(b * SEQ) + row0) * HD;
    const __half* kbase = g_kh + (size_t)b * SEQ * HD;
    const __half* vh    = g_vh + (size_t)(b * 64) * SEQ;
    float* arow = attn + ((size_t)(b * SEQ) + row0) * SEQ;
    float* sinv = (float*)(smem + SINV);
    float* ssum = (float*)(smem + SSUM);               // [2][64]

    // prologue: q tile + k tile 0
    {
#pragma unroll
        for (int i = 0; i < 2; ++i) {
            int chunk = tid + i * 256;
            int r = chunk >> 3, c = chunk & 7;
            CP_ASYNC16(sb + QT + r * 128 + ((c ^ (r & 7)) << 4),
                       qrow + (size_t)r * HD + c * 8);
        }
#pragma unroll
        for (int i = 0; i < 2; ++i) {
            int chunk = tid + i * 256;
            int r = chunk >> 3, c = chunk & 7;
            CP_ASYNC16(sb + KT + r * 128 + ((c ^ (r & 7)) << 4),
                       kbase + (size_t)r * HD + c * 8);
        }
        CP_COMMIT();
    }

    const int wm = wid >> 1, wn = wid & 1;             // 4 x 2 warps
    const int rl0 = wm * 16 + (l >> 2);
    const int sh0 = 2 * (l & 3);

    float oacc[4][4];
#pragma unroll
    for (int j = 0; j < 4; ++j)
#pragma unroll
        for (int k = 0; k < 4; ++k) oacc[j][k] = 0.f;
    float rsum[2] = { 0.f, 0.f };

    for (int it = 0; it < 64; ++it) {
        const bool p2 = it >= 32;
        const int tile = p2 ? it - 32 : it;
        const int t0 = tile * 64;
        const int buf = it & 1;

        CP_WAIT(0);
        __syncthreads();                                // tiles ready, prev reads done

        // boundary: reduce row sums -> sinv (once)
        if (it == 32) {
            float v0 = rsum[0], v1 = rsum[1];
            v0 += __shfl_xor_sync(~0u, v0, 1);
            v0 += __shfl_xor_sync(~0u, v0, 2);
            v1 += __shfl_xor_sync(~0u, v1, 1);
            v1 += __shfl_xor_sync(~0u, v1, 2);
            if ((l & 3) == 0) {
                ssum[wn * 64 + rl0]     = v0;
                ssum[wn * 64 + rl0 + 8] = v1;
            }
            __syncthreads();
            if (tid < 64)
                sinv[tid] = 1.0f / (ssum[tid] + ssum[64 + tid]);
            __syncthreads();
        }

        // prefetch next iteration's tiles
        if (it < 63) {
            const int nit = it + 1;
            const int ntile = nit >= 32 ? nit - 32 : nit;
            const int nt0 = ntile * 64;
            const int nbuf = nit & 1;
#pragma unroll
            for (int i = 0; i < 2; ++i) {
                int chunk = tid + i * 256;
                int r = chunk >> 3, c = chunk & 7;
                CP_ASYNC16(sb + KT + nbuf * 8192 + r * 128 + ((c ^ (r & 7)) << 4),
                           kbase + (size_t)(nt0 + r) * HD + c * 8);
            }
            if (nit >= 32) {
#pragma unroll
                for (int i = 0; i < 2; ++i) {
                    int chunk = tid + i * 256;
                    int r = chunk >> 3, c = chunk & 7;
                    CP_ASYNC16(sb + VT + nbuf * 8192 + r * 128 + ((c ^ (r & 7)) << 4),
                               vh + (size_t)r * SEQ + nt0 + c * 8);
                }
            }
            CP_COMMIT();
        }

        // ---- QK mma
        float sacc[4][4];
#pragma unroll
        for (int j = 0; j < 4; ++j)
#pragma unroll
            for (int k = 0; k < 4; ++k) sacc[j][k] = 0.f;

        const uint32_t Kc = sb + KT + buf * 8192;
#pragma unroll
        for (int ks = 0; ks < 4; ++ks) {
            uint32_t a[4];
            {
                int r = wm * 16 + (l & 15);
                int c = 2 * ks + (l >> 4);
                ldsm_x4(a[0], a[1], a[2], a[3],
                        sb + QT + r * 128 + ((c ^ (r & 7)) << 4));
            }
            uint32_t bh[4][2];
#pragma unroll
            for (int j = 0; j < 2; ++j) {
                int n = wn * 32 + j * 16 + (l & 7) + ((l >> 4) << 3);
                int c = 2 * ks + ((l >> 3) & 1);
                uint32_t t0r, t1r, t2r, t3r;
                ldsm_x4(t0r, t1r, t2r, t3r, Kc + n * 128 + ((c ^ (n & 7)) << 4));
                bh[j*2][0] = t0r; bh[j*2][1] = t1r; bh[j*2+1][0] = t2r; bh[j*2+1][1] = t3r;
            }
#pragma unroll
            for (int nt = 0; nt < 4; ++nt)
                mma16816h(sacc[nt], a, bh[nt]);
        }

        if (!p2) {
            // ---- pass 1 epilogue: accumulate row sums
#pragma unroll
            for (int h = 0; h < 2; ++h) {
                const int rl = rl0 + h * 8;
                const uint32_t w = g_maskbits[(size_t)(row0 + rl) * 64 + (t0 >> 5) + wn];
#pragma unroll
                for (int nt = 0; nt < 4; ++nt) {
                    const uint32_t bits = w >> (nt * 8 + sh0);
                    float e0 = (bits & 1u) ? ex2f(sacc[nt][h * 2 + 0] * LOG2E) : 0.f;
                    float e1 = (bits & 2u) ? ex2f(sacc[nt][h * 2 + 1] * LOG2E) : 0.f;
                    rsum[h] += e0 + e1;
                }
            }
        } else {
            // ---- pass 2 epilogue: p = e*inv -> attn + fp16 AP
#pragma unroll
            for (int h = 0; h < 2; ++h) {
                const int rl = rl0 + h * 8;
                const uint32_t w = g_maskbits[(size_t)(row0 + rl) * 64 + (t0 >> 5) + wn];
                const float inv = sinv[rl];
                float* gp = arow + (size_t)rl * SEQ + t0 + wn * 32 + sh0;
#pragma unroll
                for (int nt = 0; nt < 4; ++nt) {
                    const uint32_t bits = w >> (nt * 8 + sh0);
                    float p0 = (bits & 1u) ? ex2f(sacc[nt][h * 2 + 0] * LOG2E) * inv : 0.f;
                    float p1 = (bits & 2u) ? ex2f(sacc[nt][h * 2 + 1] * LOG2E) * inv : 0.f;
                    __stcs((float2*)(gp + nt * 8), make_float2(p0, p1));
                    uint32_t chunk = (uint32_t)((4 * wn + nt) ^ (rl & 7));
                    *(uint32_t*)(smem + AP + rl * 128 + chunk * 16 + 4 * (l & 3)) =
                        hpack(p0, p1);
                }
            }
            PAIR_BAR(1 + wm);                           // AP rows of this pair done

            // ---- PV mma
            const uint32_t Vc = sb + VT + buf * 8192;
#pragma unroll
            for (int ks = 0; ks < 4; ++ks) {
                uint32_t a[4];
                {
                    int r = wm * 16 + (l & 15);
                    int c = 2 * ks + (l >> 4);
                    ldsm_x4(a[0], a[1], a[2], a[3],
                            sb + AP + r * 128 + ((c ^ (r & 7)) << 4));
                }
                uint32_t bh[4][2];
#pragma unroll
                for (int j = 0; j < 2; ++j) {
                    int n = wn * 32 + j * 16 + (l & 7) + ((l >> 4) << 3);
                    int c = 2 * ks + ((l >> 3) & 1);
                    uint32_t t0r, t1r, t2r, t3r;
                    ldsm_x4(t0r, t1r, t2r, t3r, Vc + n * 128 + ((c ^ (n & 7)) << 4));
                    bh[j*2][0] = t0r; bh[j*2][1] = t1r; bh[j*2+1][0] = t2r; bh[j*2+1][1] = t3r;
                }
#pragma unroll
                for (int nt = 0; nt < 4; ++nt)
                    mma16816h(oacc[nt], a, bh[nt]);
            }
        }
    }

    // epilogue
#pragma unroll
    for (int nt = 0; nt < 4; ++nt) {
        const int gc = wn * 32 + nt * 8 + 2 * (l & 3);
#pragma unroll
        for (int h = 0; h < 2; ++h) {
            const int gr = row0 + wm * 16 + (l >> 2) + h * 8;
            *(float2*)(out + ((size_t)(b * SEQ) + gr) * HD + gc) =
                make_float2(oacc[nt][h * 2 + 0], oacc[nt][h * 2 + 1]);
        }
    }
}

// ===========================================================================
extern "C" void kernel_launch(void* const* d_in, const int* in_sizes, int n_in,
                              void* d_out, int out_size)
{
    const float* q    = (const float*)d_in[0];
    const float* k    = (const float*)d_in[1];
    const float* v    = (const float*)d_in[2];
    const int*   mask = (const int*)d_in[3];

    float* out  = (float*)d_out;
    float* attn = out + (size_t)BATCH * SEQ * HD;

    cudaFuncSetAttribute(attn_fused_kernel,
                         cudaFuncAttributeMaxDynamicSharedMemorySize, 49920);

    prep_kernel<<<dim3(512, 3), 256>>>((const float4*)q, (const float4*)k, v, mask);

    attn_fused_kernel<<<dim3(32, BATCH), 256, 49920>>>(attn, out);
}

// round 16
// speedup vs baseline: 1.0813x; 1.0813x over previous
#include <cuda_runtime.h>
#include <cuda_fp16.h>
#include <cstdint>

#define SEQ   2048
#define HD    64
#define BATCH 16

// ---------------------------------------------------------------------------
// device scratch
// ---------------------------------------------------------------------------
__device__ __half    g_qh[BATCH * SEQ * HD];        // fp16(q / 8)
__device__ __half    g_kh[BATCH * SEQ * HD];        // fp16(k)
__device__ __half    g_vh[BATCH * HD * SEQ];        // transposed [b][d][t], fp16
__device__ float     g_part[BATCH * SEQ * 32];      // per-row per-coltile exp sums
__device__ uint32_t  g_maskbits[SEQ * (SEQ / 32)];

#define LOG2E 1.4426950408889634f

// ---------------------------------------------------------------------------
// helpers
// ---------------------------------------------------------------------------
__device__ __forceinline__ uint32_t smem_u32(const void* p) {
    uint32_t a;
    asm("{ .reg .u64 t; cvta.to.shared.u64 t, %1; cvt.u32.u64 %0, t; }" : "=r"(a) : "l"(p));
    return a;
}
__device__ __forceinline__ uint32_t hpack(float a, float b) {
    uint32_t r;
    asm("cvt.rn.f16x2.f32 %0, %1, %2;" : "=r"(r) : "f"(b), "f"(a));
    return r;
}
__device__ __forceinline__ float ex2f(float x) {
    float r;
    asm("ex2.approx.ftz.f32 %0, %1;" : "=f"(r) : "f"(x));
    return r;
}
__device__ __forceinline__ void ldsm_x4(uint32_t& r0, uint32_t& r1, uint32_t& r2,
                                        uint32_t& r3, uint32_t addr) {
    asm volatile("ldmatrix.sync.aligned.m8n8.x4.shared.b16 {%0,%1,%2,%3}, [%4];"
                 : "=r"(r0), "=r"(r1), "=r"(r2), "=r"(r3) : "r"(addr));
}
__device__ __forceinline__ void mma16816h(float* c, const uint32_t* a, const uint32_t* b) {
    asm volatile("mma.sync.aligned.m16n8k16.row.col.f32.f16.f16.f32 "
                 "{%0,%1,%2,%3}, {%4,%5,%6,%7}, {%8,%9}, {%0,%1,%2,%3};"
                 : "+f"(c[0]), "+f"(c[1]), "+f"(c[2]), "+f"(c[3])
                 : "r"(a[0]), "r"(a[1]), "r"(a[2]), "r"(a[3]), "r"(b[0]), "r"(b[1]));
}
#define CP_ASYNC16(dst, src) \
    asm volatile("cp.async.cg.shared.global [%0], [%1], 16;" :: "r"(dst), "l"(src))
#define CP_COMMIT()  asm volatile("cp.async.commit_group;" ::: "memory")
#define CP_WAIT(n)   asm volatile("cp.async.wait_group %0;" :: "n"(n) : "memory")
#define PAIR_BAR(id) asm volatile("bar.sync %0, 64;" :: "r"(id) : "memory")

// ===========================================================================
// fused prep: y=0 mask pack | y=1 q/8, k fp16 convert | y=2 v transpose fp16
// ===========================================================================
__global__ void __launch_bounds__(256) prep_kernel(
    const float4* __restrict__ q, const float4* __restrict__ k,
    const float* __restrict__ v, const int* __restrict__ mask)
{
    __shared__ float sm[64][129];            // used only by y == 2
    const int tid = threadIdx.x;

    if (blockIdx.y == 0) {
        const int gw = (blockIdx.x * 256 + tid) >> 5;
        const int l  = tid & 31;
        const int nwarps = gridDim.x * 8;
        const int ngroups = SEQ * (SEQ / 32) / 4;      // 32768
        for (int g = gw; g < ngroups; g += nwarps) {
            int4 mv = *(const int4*)(mask + (size_t)128 * g + 4 * l);
            uint32_t nib = (uint32_t)(mv.x != 0) | ((uint32_t)(mv.y != 0) << 1) |
                           ((uint32_t)(mv.z != 0) << 2) | ((uint32_t)(mv.w != 0) << 3);
            uint32_t bits = nib << (4 * (l & 7));
            bits |= __shfl_xor_sync(~0u, bits, 1);
            bits |= __shfl_xor_sync(~0u, bits, 2);
            bits |= __shfl_xor_sync(~0u, bits, 4);
            if ((l & 7) == 0) g_maskbits[4 * g + (l >> 3)] = bits;
        }
    } else if (blockIdx.y == 1) {
        const int isK = blockIdx.x >= 256;
        const float4* src = isK ? k : q;
        uint2* hi = (uint2*)(isK ? g_kh : g_qh);
        const float scale = isK ? 1.0f : 0.125f;
        const int n = BATCH * SEQ * HD / 4;
        const int stride = 256 * 256;
        for (int c = (blockIdx.x & 255) * 256 + tid; c < n; c += stride) {
            float4 x = src[c];
            hi[c] = make_uint2(hpack(x.x * scale, x.y * scale),
                               hpack(x.z * scale, x.w * scale));
        }
    } else {
        if (blockIdx.x >= 256) return;
        const int b = blockIdx.x >> 4, t0 = (blockIdx.x & 15) * 128;
        const float* vb = v + (size_t)b * SEQ * HD;
#pragma unroll
        for (int i = 0; i < 8; ++i) {
            int chunk = tid + i * 256;
            int t = chunk >> 4, d4 = (chunk & 15) * 4;
            float4 x = *(const float4*)(vb + (size_t)(t0 + t) * HD + d4);
            sm[d4 + 0][t] = x.x; sm[d4 + 1][t] = x.y;
            sm[d4 + 2][t] = x.z; sm[d4 + 3][t] = x.w;
        }
        __syncthreads();
        const int r = tid >> 2, tb = (tid & 3) * 32;
        size_t obase = ((size_t)(b * 64 + r)) * SEQ + t0 + tb;
#pragma unroll
        for (int seg = 0; seg < 4; ++seg) {
            uint32_t h[4];
#pragma unroll
            for (int j = 0; j < 4; ++j)
                h[j] = hpack(sm[r][tb + seg * 8 + j * 2],
                             sm[r][tb + seg * 8 + j * 2 + 1]);
            *(uint4*)(g_vh + obase + seg * 8) = make_uint4(h[0], h[1], h[2], h[3]);
        }
    }
}

// ===========================================================================
// scores: row-sum-only pass. CTA 128 rows x 64 cols -> g_part[row][32]
// ===========================================================================
__global__ void __launch_bounds__(256, 3) scores_mma_kernel()
{
    extern __shared__ char smem[];
    constexpr int AHI = 0, BHI = 16384;
    const uint32_t sb = smem_u32(smem);
    const int tid = threadIdx.x, wid = tid >> 5, l = tid & 31;
    const int b = blockIdx.z, row0 = blockIdx.y * 128, col0 = blockIdx.x * 64;

    {
        const __half* asrc = g_qh + ((size_t)(b * SEQ) + row0) * HD;
#pragma unroll
        for (int i = 0; i < 4; ++i) {
            int chunk = tid + i * 256;
            int r = chunk >> 3, c = chunk & 7;
            *(uint4*)(smem + AHI + r * 128 + ((c ^ (r & 7)) << 4)) =
                *(const uint4*)(asrc + (size_t)r * HD + c * 8);
        }
        const __half* bsrc = g_kh + ((size_t)(b * SEQ) + col0) * HD;
#pragma unroll
        for (int i = 0; i < 2; ++i) {
            int chunk = tid + i * 256;
            int r = chunk >> 3, c = chunk & 7;
            *(uint4*)(smem + BHI + r * 128 + ((c ^ (r & 7)) << 4)) =
                *(const uint4*)(bsrc + (size_t)r * HD + c * 8);
        }
    }
    __syncthreads();

    const int wm = wid >> 1, wn = wid & 1;           // 4 x 2 warps, tile 32x32
    float acc[2][4][4];
#pragma unroll
    for (int i = 0; i < 2; ++i)
#pragma unroll
        for (int j = 0; j < 4; ++j)
#pragma unroll
            for (int k = 0; k < 4; ++k) acc[i][j][k] = 0.f;

#pragma unroll
    for (int ks = 0; ks < 4; ++ks) {
        uint32_t a[2][4];
#pragma unroll
        for (int mt = 0; mt < 2; ++mt) {
            int r = wm * 32 + mt * 16 + (l & 15);
            int c = 2 * ks + (l >> 4);
            ldsm_x4(a[mt][0], a[mt][1], a[mt][2], a[mt][3],
                    sb + AHI + r * 128 + ((c ^ (r & 7)) << 4));
        }
        uint32_t bh[4][2];
#pragma unroll
        for (int j = 0; j < 2; ++j) {
            int n = wn * 32 + j * 16 + (l & 7) + ((l >> 4) << 3);
            int c = 2 * ks + ((l >> 3) & 1);
            uint32_t t0, t1, t2, t3;
            ldsm_x4(t0, t1, t2, t3, sb + BHI + n * 128 + ((c ^ (n & 7)) << 4));
            bh[j*2][0] = t0; bh[j*2][1] = t1; bh[j*2+1][0] = t2; bh[j*2+1][1] = t3;
        }
#pragma unroll
        for (int mt = 0; mt < 2; ++mt)
#pragma unroll
            for (int nt = 0; nt < 4; ++nt)
                mma16816h(acc[mt][nt], a[mt], bh[nt]);
    }

    __syncthreads();
    float* srow = (float*)smem;      // [2][128]

    float rs[2][2];
    rs[0][0] = rs[0][1] = rs[1][0] = rs[1][1] = 0.f;

    const int wbase = (col0 >> 5) + wn;
#pragma unroll
    for (int mt = 0; mt < 2; ++mt) {
#pragma unroll
        for (int h = 0; h < 2; ++h) {
            const int s = row0 + wm * 32 + mt * 16 + (l >> 2) + h * 8;
            const uint32_t w = g_maskbits[(size_t)s * 64 + wbase];
            const int sh0 = 2 * (l & 3);
#pragma unroll
            for (int nt = 0; nt < 4; ++nt) {
                const uint32_t bits = w >> (nt * 8 + sh0);
                float e0 = (bits & 1u) ? ex2f(acc[mt][nt][h * 2 + 0] * LOG2E) : 0.f;
                float e1 = (bits & 2u) ? ex2f(acc[mt][nt][h * 2 + 1] * LOG2E) : 0.f;
                rs[mt][h] += e0 + e1;
            }
        }
    }
#pragma unroll
    for (int mt = 0; mt < 2; ++mt)
#pragma unroll
        for (int h = 0; h < 2; ++h) {
            float v = rs[mt][h];
            v += __shfl_xor_sync(~0u, v, 1);
            v += __shfl_xor_sync(~0u, v, 2);
            rs[mt][h] = v;
        }
    if ((l & 3) == 0) {
#pragma unroll
        for (int mt = 0; mt < 2; ++mt)
#pragma unroll
            for (int h = 0; h < 2; ++h)
                srow[wn * 128 + wm * 32 + mt * 16 + (l >> 2) + h * 8] = rs[mt][h];
    }
    __syncthreads();
    if (tid < 128) {
        float s = srow[tid] + srow[128 + tid];
        g_part[((size_t)(b * SEQ) + row0 + tid) * 32 + blockIdx.x] = s;
    }
}

// ===========================================================================
// pv (register repack): warps split the t dimension (wn's 32-t slice).
// Per 64-col k-tile: QK mma -> p (fp32 attn write) -> repack p into PV A
// fragments IN REGISTERS -> PV mma over all 64 d (partial K). Pair-reduce
// oacc at the end. No AP smem, no per-tile pair barrier.
// smem: QT 8K | KT 2x8K | VT 2x8K | SINV 256  (RED reuses KT after loop)
// ===========================================================================
__global__ void __launch_bounds__(256, 2) pv_mma_kernel(
    float* __restrict__ attn, float* __restrict__ out)
{
    extern __shared__ char smem[];
    constexpr int QT = 0, KT = 8192, VT = 24576, SINV = 40960, RED = 8192;
    const uint32_t sb = smem_u32(smem);
    const int tid = threadIdx.x, wid = tid >> 5, l = tid & 31;
    const int b = blockIdx.y, row0 = blockIdx.x * 64;

    float* sinv = (float*)(smem + SINV);
    if (tid < 64) {
        const float4* pp = (const float4*)(g_part + ((size_t)(b * SEQ) + row0 + tid) * 32);
        float s = 0.f;
#pragma unroll
        for (int i = 0; i < 8; ++i) {
            float4 t = pp[i];
            s += (t.x + t.y) + (t.z + t.w);
        }
        sinv[tid] = 1.0f / s;
    }

    const __half* qrow  = g_qh + ((size_t)(b * SEQ) + row0) * HD;
    const __half* kbase = g_kh + (size_t)b * SEQ * HD;
    const __half* vh    = g_vh + (size_t)(b * 64) * SEQ;
    float* arow = attn + ((size_t)(b * SEQ) + row0) * SEQ;

    // prologue: q tile + k/v tile 0
    {
#pragma unroll
        for (int i = 0; i < 2; ++i) {
            int chunk = tid + i * 256;
            int r = chunk >> 3, c = chunk & 7;
            CP_ASYNC16(sb + QT + r * 128 + ((c ^ (r & 7)) << 4),
                       qrow + (size_t)r * HD + c * 8);
        }
#pragma unroll
        for (int i = 0; i < 2; ++i) {
            int chunk = tid + i * 256;
            int r = chunk >> 3, c = chunk & 7;
            CP_ASYNC16(sb + KT + r * 128 + ((c ^ (r & 7)) << 4),
                       kbase + (size_t)r * HD + c * 8);
        }
#pragma unroll
        for (int i = 0; i < 2; ++i) {
            int chunk = tid + i * 256;
            int r = chunk >> 3, c = chunk & 7;
            CP_ASYNC16(sb + VT + r * 128 + ((c ^ (r & 7)) << 4),
                       vh + (size_t)r * SEQ + c * 8);
        }
        CP_COMMIT();
    }

    const int wm = wid >> 1, wn = wid & 1;             // 4 row-pairs x 2 t-slices
    const int rl0 = wm * 16 + (l >> 2);
    const int sh0 = 2 * (l & 3);

    float oacc[8][4];                                   // all 64 d cols, partial K
#pragma unroll
    for (int j = 0; j < 8; ++j)
#pragma unroll
        for (int k = 0; k < 4; ++k) oacc[j][k] = 0.f;

    for (int tile = 0; tile < 32; ++tile) {
        const int t0 = tile * 64;
        const int buf = tile & 1;

        CP_WAIT(0);
        __syncthreads();                                // tiles ready

        if (tile < 31) {
            const int nt0 = t0 + 64;
            const int nbuf = buf ^ 1;
#pragma unroll
            for (int i = 0; i < 2; ++i) {
                int chunk = tid + i * 256;
                int r = chunk >> 3, c = chunk & 7;
                CP_ASYNC16(sb + KT + nbuf * 8192 + r * 128 + ((c ^ (r & 7)) << 4),
                           kbase + (size_t)(nt0 + r) * HD + c * 8);
            }
#pragma unroll
            for (int i = 0; i < 2; ++i) {
                int chunk = tid + i * 256;
                int r = chunk >> 3, c = chunk & 7;
                CP_ASYNC16(sb + VT + nbuf * 8192 + r * 128 + ((c ^ (r & 7)) << 4),
                           vh + (size_t)r * SEQ + nt0 + c * 8);
            }
            CP_COMMIT();
        }

        // ---- QK mma: this warp's 16-row x 32-t slice
        float sacc[4][4];
#pragma unroll
        for (int j = 0; j < 4; ++j)
#pragma unroll
            for (int k = 0; k < 4; ++k) sacc[j][k] = 0.f;

        const uint32_t Kc = sb + KT + buf * 8192;
#pragma unroll
        for (int ks = 0; ks < 4; ++ks) {
            uint32_t a[4];
            {
                int r = wm * 16 + (l & 15);
                int c = 2 * ks + (l >> 4);
                ldsm_x4(a[0], a[1], a[2], a[3],
                        sb + QT + r * 128 + ((c ^ (r & 7)) << 4));
            }
            uint32_t bh[4][2];
#pragma unroll
            for (int j = 0; j < 2; ++j) {
                int n = wn * 32 + j * 16 + (l & 7) + ((l >> 4) << 3);
                int c = 2 * ks + ((l >> 3) & 1);
                uint32_t t0r, t1r, t2r, t3r;
                ldsm_x4(t0r, t1r, t2r, t3r, Kc + n * 128 + ((c ^ (n & 7)) << 4));
                bh[j*2][0] = t0r; bh[j*2][1] = t1r; bh[j*2+1][0] = t2r; bh[j*2+1][1] = t3r;
            }
#pragma unroll
            for (int nt = 0; nt < 4; ++nt)
                mma16816h(sacc[nt], a, bh[nt]);
        }

        // ---- epilogue: p = mask ? exp*inv : 0 -> attn (fp32) + A frags (regs)
        uint32_t pa[2][4];                              // [ksl][a-frag]
#pragma unroll
        for (int h = 0; h < 2; ++h) {
            const int rl = rl0 + h * 8;
            const uint32_t w = g_maskbits[(size_t)(row0 + rl) * 64 + (t0 >> 5) + wn];
            const float inv = sinv[rl];
            float* gp = arow + (size_t)rl * SEQ + t0 + wn * 32 + sh0;
#pragma unroll
            for (int nt = 0; nt < 4; ++nt) {
                const uint32_t bits = w >> (nt * 8 + sh0);
                float p0 = (bits & 1u) ? ex2f(sacc[nt][h * 2 + 0] * LOG2E) * inv : 0.f;
                float p1 = (bits & 2u) ? ex2f(sacc[nt][h * 2 + 1] * LOG2E) * inv : 0.f;
                __stcs((float2*)(gp + nt * 8), make_float2(p0, p1));
                pa[nt >> 1][(nt & 1) * 2 + h] = hpack(p0, p1);
            }
        }

        // ---- PV mma: oacc[all 64 d] += p(16x32) @ v(32x64), K split by wn
        const uint32_t Vc = sb + VT + buf * 8192;
#pragma unroll
        for (int ksl = 0; ksl < 2; ++ksl) {
            const int c = 2 * (wn * 2 + ksl) + ((l >> 3) & 1);
            uint32_t bh[8][2];
#pragma unroll
            for (int j = 0; j < 4; ++j) {
                int n = j * 16 + (l & 7) + ((l >> 4) << 3);
                uint32_t t0r, t1r, t2r, t3r;
                ldsm_x4(t0r, t1r, t2r, t3r, Vc + n * 128 + ((c ^ (n & 7)) << 4));
                bh[j*2][0] = t0r; bh[j*2][1] = t1r; bh[j*2+1][0] = t2r; bh[j*2+1][1] = t3r;
            }
#pragma unroll
            for (int nt2 = 0; nt2 < 8; ++nt2)
                mma16816h(oacc[nt2], pa[ksl], bh[nt2]);
        }
    }

    // ---- pair reduction (wn=1 partial -> smem -> wn=0 adds) + store
    __syncthreads();                                    // KT/VT dead, reuse as RED
    float* red = (float*)(smem + RED);                  // [64][64]
    if (wn == 1) {
#pragma unroll
        for (int nt2 = 0; nt2 < 8; ++nt2) {
            const int gc = nt2 * 8 + sh0;
#pragma unroll
            for (int h = 0; h < 2; ++h) {
                const int rl = rl0 + h * 8;
                *(float2*)(red + rl * 64 + gc) =
                    make_float2(oacc[nt2][h * 2 + 0], oacc[nt2][h * 2 + 1]);
            }
        }
    }
    __syncthreads();
    if (wn == 0) {
#pragma unroll
        for (int nt2 = 0; nt2 < 8; ++nt2) {
            const int gc = nt2 * 8 + sh0;
#pragma unroll
            for (int h = 0; h < 2; ++h) {
                const int rl = rl0 + h * 8;
                float2 o = *(const float2*)(red + rl * 64 + gc);
                *(float2*)(out + ((size_t)(b * SEQ) + row0 + rl) * HD + gc) =
                    make_float2(oacc[nt2][h * 2 + 0] + o.x,
                                oacc[nt2][h * 2 + 1] + o.y);
            }
        }
    }
}

// ===========================================================================
extern "C" void kernel_launch(void* const* d_in, const int* in_sizes, int n_in,
                              void* d_out, int out_size)
{
    const float* q    = (const float*)d_in[0];
    const float* k    = (const float*)d_in[1];
    const float* v    = (const float*)d_in[2];
    const int*   mask = (const int*)d_in[3];

    float* out  = (float*)d_out;
    float* attn = out + (size_t)BATCH * SEQ * HD;

    cudaFuncSetAttribute(scores_mma_kernel,
                         cudaFuncAttributeMaxDynamicSharedMemorySize, 24576);
    cudaFuncSetAttribute(pv_mma_kernel,
                         cudaFuncAttributeMaxDynamicSharedMemorySize, 41216);

    prep_kernel<<<dim3(512, 3), 256>>>((const float4*)q, (const float4*)k, v, mask);

    scores_mma_kernel<<<dim3(32, 16, BATCH), 256, 24576>>>();
    pv_mma_kernel<<<dim3(32, BATCH), 256, 41216>>>(attn, out);
}

// round 17
// speedup vs baseline: 1.1345x; 1.0492x over previous
#include <cuda_runtime.h>
#include <cuda_fp16.h>
#include <cstdint>

#define SEQ   2048
#define HD    64
#define BATCH 16

// ---------------------------------------------------------------------------
// device scratch
// ---------------------------------------------------------------------------
__device__ __half    g_qh[BATCH * SEQ * HD];        // fp16(q / 8)
__device__ __half    g_kh[BATCH * SEQ * HD];        // fp16(k)
__device__ __half    g_vh[BATCH * HD * SEQ];        // transposed [b][d][t], fp16
__device__ float     g_part[BATCH * SEQ * 32];      // per-row per-coltile exp sums
__device__ uint32_t  g_maskbits[SEQ * (SEQ / 32)];

#define LOG2E 1.4426950408889634f

// ---------------------------------------------------------------------------
// helpers
// ---------------------------------------------------------------------------
__device__ __forceinline__ uint32_t smem_u32(const void* p) {
    uint32_t a;
    asm("{ .reg .u64 t; cvta.to.shared.u64 t, %1; cvt.u32.u64 %0, t; }" : "=r"(a) : "l"(p));
    return a;
}
__device__ __forceinline__ uint32_t hpack(float a, float b) {
    uint32_t r;
    asm("cvt.rn.f16x2.f32 %0, %1, %2;" : "=r"(r) : "f"(b), "f"(a));
    return r;
}
__device__ __forceinline__ float ex2f(float x) {
    float r;
    asm("ex2.approx.ftz.f32 %0, %1;" : "=f"(r) : "f"(x));
    return r;
}
__device__ __forceinline__ void ldsm_x4(uint32_t& r0, uint32_t& r1, uint32_t& r2,
                                        uint32_t& r3, uint32_t addr) {
    asm volatile("ldmatrix.sync.aligned.m8n8.x4.shared.b16 {%0,%1,%2,%3}, [%4];"
                 : "=r"(r0), "=r"(r1), "=r"(r2), "=r"(r3) : "r"(addr));
}
__device__ __forceinline__ void mma16816h(float* c, const uint32_t* a, const uint32_t* b) {
    asm volatile("mma.sync.aligned.m16n8k16.row.col.f32.f16.f16.f32 "
                 "{%0,%1,%2,%3}, {%4,%5,%6,%7}, {%8,%9}, {%0,%1,%2,%3};"
                 : "+f"(c[0]), "+f"(c[1]), "+f"(c[2]), "+f"(c[3])
                 : "r"(a[0]), "r"(a[1]), "r"(a[2]), "r"(a[3]), "r"(b[0]), "r"(b[1]));
}
#define CP_ASYNC16(dst, src) \
    asm volatile("cp.async.cg.shared.global [%0], [%1], 16;" :: "r"(dst), "l"(src))
#define CP_COMMIT()  asm volatile("cp.async.commit_group;" ::: "memory")
#define CP_WAIT(n)   asm volatile("cp.async.wait_group %0;" :: "n"(n) : "memory")

// ===========================================================================
// fused prep: y=0 mask pack | y=1 q/8, k fp16 convert | y=2 v transpose fp16
// ===========================================================================
__global__ void __launch_bounds__(256) prep_kernel(
    const float4* __restrict__ q, const float4* __restrict__ k,
    const float* __restrict__ v, const int* __restrict__ mask)
{
    __shared__ float sm[64][129];            // used only by y == 2
    const int tid = threadIdx.x;

    if (blockIdx.y == 0) {
        const int gw = (blockIdx.x * 256 + tid) >> 5;
        const int l  = tid & 31;
        const int nwarps = gridDim.x * 8;
        const int ngroups = SEQ * (SEQ / 32) / 4;      // 32768
        for (int g = gw; g < ngroups; g += nwarps) {
            int4 mv = *(const int4*)(mask + (size_t)128 * g + 4 * l);
            uint32_t nib = (uint32_t)(mv.x != 0) | ((uint32_t)(mv.y != 0) << 1) |
                           ((uint32_t)(mv.z != 0) << 2) | ((uint32_t)(mv.w != 0) << 3);
            uint32_t bits = nib << (4 * (l & 7));
            bits |= __shfl_xor_sync(~0u, bits, 1);
            bits |= __shfl_xor_sync(~0u, bits, 2);
            bits |= __shfl_xor_sync(~0u, bits, 4);
            if ((l & 7) == 0) g_maskbits[4 * g + (l >> 3)] = bits;
        }
    } else if (blockIdx.y == 1) {
        const int isK = blockIdx.x >= 256;
        const float4* src = isK ? k : q;
        uint2* hi = (uint2*)(isK ? g_kh : g_qh);
        const float scale = isK ? 1.0f : 0.125f;
        const int n = BATCH * SEQ * HD / 4;
        const int stride = 256 * 256;
        // 2 independent chunks in flight per iteration
        for (int c = (blockIdx.x & 255) * 256 + tid; c < n; c += 2 * stride) {
            float4 x0 = src[c];
            const int c1 = c + stride;
            float4 x1 = (c1 < n) ? src[c1] : make_float4(0.f, 0.f, 0.f, 0.f);
            hi[c] = make_uint2(hpack(x0.x * scale, x0.y * scale),
                               hpack(x0.z * scale, x0.w * scale));
            if (c1 < n)
                hi[c1] = make_uint2(hpack(x1.x * scale, x1.y * scale),
                                    hpack(x1.z * scale, x1.w * scale));
        }
    } else {
        if (blockIdx.x >= 256) return;
        const int b = blockIdx.x >> 4, t0 = (blockIdx.x & 15) * 128;
        const float* vb = v + (size_t)b * SEQ * HD;
#pragma unroll
        for (int i = 0; i < 8; ++i) {
            int chunk = tid + i * 256;
            int t = chunk >> 4, d4 = (chunk & 15) * 4;
            float4 x = *(const float4*)(vb + (size_t)(t0 + t) * HD + d4);
            sm[d4 + 0][t] = x.x; sm[d4 + 1][t] = x.y;
            sm[d4 + 2][t] = x.z; sm[d4 + 3][t] = x.w;
        }
        __syncthreads();
        const int r = tid >> 2, tb = (tid & 3) * 32;
        size_t obase = ((size_t)(b * 64 + r)) * SEQ + t0 + tb;
#pragma unroll
        for (int seg = 0; seg < 4; ++seg) {
            uint32_t h[4];
#pragma unroll
            for (int j = 0; j < 4; ++j)
                h[j] = hpack(sm[r][tb + seg * 8 + j * 2],
                             sm[r][tb + seg * 8 + j * 2 + 1]);
            *(uint4*)(g_vh + obase + seg * 8) = make_uint4(h[0], h[1], h[2], h[3]);
        }
    }
}

// ===========================================================================
// scores: row-sum-only pass. CTA 128 rows x 64 cols -> g_part[row][32]
// ===========================================================================
__global__ void __launch_bounds__(256, 3) scores_mma_kernel()
{
    extern __shared__ char smem[];
    constexpr int AHI = 0, BHI = 16384;
    const uint32_t sb = smem_u32(smem);
    const int tid = threadIdx.x, wid = tid >> 5, l = tid & 31;
    const int b = blockIdx.z, row0 = blockIdx.y * 128, col0 = blockIdx.x * 64;

    {
        const __half* asrc = g_qh + ((size_t)(b * SEQ) + row0) * HD;
#pragma unroll
        for (int i = 0; i < 4; ++i) {
            int chunk = tid + i * 256;
            int r = chunk >> 3, c = chunk & 7;
            *(uint4*)(smem + AHI + r * 128 + ((c ^ (r & 7)) << 4)) =
                *(const uint4*)(asrc + (size_t)r * HD + c * 8);
        }
        const __half* bsrc = g_kh + ((size_t)(b * SEQ) + col0) * HD;
#pragma unroll
        for (int i = 0; i < 2; ++i) {
            int chunk = tid + i * 256;
            int r = chunk >> 3, c = chunk & 7;
            *(uint4*)(smem + BHI + r * 128 + ((c ^ (r & 7)) << 4)) =
                *(const uint4*)(bsrc + (size_t)r * HD + c * 8);
        }
    }
    __syncthreads();

    const int wm = wid >> 1, wn = wid & 1;           // 4 x 2 warps, tile 32x32
    float acc[2][4][4];
#pragma unroll
    for (int i = 0; i < 2; ++i)
#pragma unroll
        for (int j = 0; j < 4; ++j)
#pragma unroll
            for (int k = 0; k < 4; ++k) acc[i][j][k] = 0.f;

#pragma unroll
    for (int ks = 0; ks < 4; ++ks) {
        uint32_t a[2][4];
#pragma unroll
        for (int mt = 0; mt < 2; ++mt) {
            int r = wm * 32 + mt * 16 + (l & 15);
            int c = 2 * ks + (l >> 4);
            ldsm_x4(a[mt][0], a[mt][1], a[mt][2], a[mt][3],
                    sb + AHI + r * 128 + ((c ^ (r & 7)) << 4));
        }
        uint32_t bh[4][2];
#pragma unroll
        for (int j = 0; j < 2; ++j) {
            int n = wn * 32 + j * 16 + (l & 7) + ((l >> 4) << 3);
            int c = 2 * ks + ((l >> 3) & 1);
            uint32_t t0, t1, t2, t3;
            ldsm_x4(t0, t1, t2, t3, sb + BHI + n * 128 + ((c ^ (n & 7)) << 4));
            bh[j*2][0] = t0; bh[j*2][1] = t1; bh[j*2+1][0] = t2; bh[j*2+1][1] = t3;
        }
#pragma unroll
        for (int mt = 0; mt < 2; ++mt)
#pragma unroll
            for (int nt = 0; nt < 4; ++nt)
                mma16816h(acc[mt][nt], a[mt], bh[nt]);
    }

    __syncthreads();
    float* srow = (float*)smem;      // [2][128]

    float rs[2][2];
    rs[0][0] = rs[0][1] = rs[1][0] = rs[1][1] = 0.f;

    const int wbase = (col0 >> 5) + wn;
#pragma unroll
    for (int mt = 0; mt < 2; ++mt) {
#pragma unroll
        for (int h = 0; h < 2; ++h) {
            const int s = row0 + wm * 32 + mt * 16 + (l >> 2) + h * 8;
            const uint32_t w = g_maskbits[(size_t)s * 64 + wbase];
            const int sh0 = 2 * (l & 3);
#pragma unroll
            for (int nt = 0; nt < 4; ++nt) {
                const uint32_t bits = w >> (nt * 8 + sh0);
                float e0 = (bits & 1u) ? ex2f(acc[mt][nt][h * 2 + 0] * LOG2E) : 0.f;
                float e1 = (bits & 2u) ? ex2f(acc[mt][nt][h * 2 + 1] * LOG2E) : 0.f;
                rs[mt][h] += e0 + e1;
            }
        }
    }
#pragma unroll
    for (int mt = 0; mt < 2; ++mt)
#pragma unroll
        for (int h = 0; h < 2; ++h) {
            float v = rs[mt][h];
            v += __shfl_xor_sync(~0u, v, 1);
            v += __shfl_xor_sync(~0u, v, 2);
            rs[mt][h] = v;
        }
    if ((l & 3) == 0) {
#pragma unroll
        for (int mt = 0; mt < 2; ++mt)
#pragma unroll
            for (int h = 0; h < 2; ++h)
                srow[wn * 128 + wm * 32 + mt * 16 + (l >> 2) + h * 8] = rs[mt][h];
    }
    __syncthreads();
    if (tid < 128) {
        float s = srow[tid] + srow[128 + tid];
        g_part[((size_t)(b * SEQ) + row0 + tid) * 32 + blockIdx.x] = s;
    }
}

// ===========================================================================
// pv (register repack + hoisted Q frags): warps split the t dimension.
// Q A-fragments loaded ONCE (loop-invariant), kept in registers.
// Per 64-col k-tile: QK mma -> p (fp32 attn write) -> repack p into PV A
// fragments in regs -> PV mma over all 64 d (partial K). Pair-reduce at end.
// smem: QT 8K | KT 2x8K | VT 2x8K | SINV 256  (RED reuses KT after loop)
// ===========================================================================
__global__ void __launch_bounds__(256, 2) pv_mma_kernel(
    float* __restrict__ attn, float* __restrict__ out)
{
    extern __shared__ char smem[];
    constexpr int QT = 0, KT = 8192, VT = 24576, SINV = 40960, RED = 8192;
    const uint32_t sb = smem_u32(smem);
    const int tid = threadIdx.x, wid = tid >> 5, l = tid & 31;
    const int b = blockIdx.y, row0 = blockIdx.x * 64;

    float* sinv = (float*)(smem + SINV);
    if (tid < 64) {
        const float4* pp = (const float4*)(g_part + ((size_t)(b * SEQ) + row0 + tid) * 32);
        float s = 0.f;
#pragma unroll
        for (int i = 0; i < 8; ++i) {
            float4 t = pp[i];
            s += (t.x + t.y) + (t.z + t.w);
        }
        sinv[tid] = 1.0f / s;
    }

    const __half* qrow  = g_qh + ((size_t)(b * SEQ) + row0) * HD;
    const __half* kbase = g_kh + (size_t)b * SEQ * HD;
    const __half* vh    = g_vh + (size_t)(b * 64) * SEQ;
    float* arow = attn + ((size_t)(b * SEQ) + row0) * SEQ;

    // prologue: q tile + k/v tile 0
    {
#pragma unroll
        for (int i = 0; i < 2; ++i) {
            int chunk = tid + i * 256;
            int r = chunk >> 3, c = chunk & 7;
            CP_ASYNC16(sb + QT + r * 128 + ((c ^ (r & 7)) << 4),
                       qrow + (size_t)r * HD + c * 8);
        }
#pragma unroll
        for (int i = 0; i < 2; ++i) {
            int chunk = tid + i * 256;
            int r = chunk >> 3, c = chunk & 7;
            CP_ASYNC16(sb + KT + r * 128 + ((c ^ (r & 7)) << 4),
                       kbase + (size_t)r * HD + c * 8);
        }
#pragma unroll
        for (int i = 0; i < 2; ++i) {
            int chunk = tid + i * 256;
            int r = chunk >> 3, c = chunk & 7;
            CP_ASYNC16(sb + VT + r * 128 + ((c ^ (r & 7)) << 4),
                       vh + (size_t)r * SEQ + c * 8);
        }
        CP_COMMIT();
    }

    const int wm = wid >> 1, wn = wid & 1;             // 4 row-pairs x 2 t-slices
    const int rl0 = wm * 16 + (l >> 2);
    const int sh0 = 2 * (l & 3);

    float oacc[8][4];                                   // all 64 d cols, partial K
#pragma unroll
    for (int j = 0; j < 8; ++j)
#pragma unroll
        for (int k = 0; k < 4; ++k) oacc[j][k] = 0.f;

    uint32_t aq[4][4];                                  // hoisted Q fragments

    for (int tile = 0; tile < 32; ++tile) {
        const int t0 = tile * 64;
        const int buf = tile & 1;

        CP_WAIT(0);
        __syncthreads();                                // tiles ready

        if (tile == 0) {
            // load Q fragments once (loop-invariant)
#pragma unroll
            for (int ks = 0; ks < 4; ++ks) {
                int r = wm * 16 + (l & 15);
                int c = 2 * ks + (l >> 4);
                ldsm_x4(aq[ks][0], aq[ks][1], aq[ks][2], aq[ks][3],
                        sb + QT + r * 128 + ((c ^ (r & 7)) << 4));
            }
        }

        if (tile < 31) {
            const int nt0 = t0 + 64;
            const int nbuf = buf ^ 1;
#pragma unroll
            for (int i = 0; i < 2; ++i) {
                int chunk = tid + i * 256;
                int r = chunk >> 3, c = chunk & 7;
                CP_ASYNC16(sb + KT + nbuf * 8192 + r * 128 + ((c ^ (r & 7)) << 4),
                           kbase + (size_t)(nt0 + r) * HD + c * 8);
            }
#pragma unroll
            for (int i = 0; i < 2; ++i) {
                int chunk = tid + i * 256;
                int r = chunk >> 3, c = chunk & 7;
                CP_ASYNC16(sb + VT + nbuf * 8192 + r * 128 + ((c ^ (r & 7)) << 4),
                           vh + (size_t)r * SEQ + nt0 + c * 8);
            }
            CP_COMMIT();
        }

        // ---- QK mma: this warp's 16-row x 32-t slice
        float sacc[4][4];
#pragma unroll
        for (int j = 0; j < 4; ++j)
#pragma unroll
            for (int k = 0; k < 4; ++k) sacc[j][k] = 0.f;

        const uint32_t Kc = sb + KT + buf * 8192;
#pragma unroll
        for (int ks = 0; ks < 4; ++ks) {
            uint32_t bh[4][2];
#pragma unroll
            for (int j = 0; j < 2; ++j) {
                int n = wn * 32 + j * 16 + (l & 7) + ((l >> 4) << 3);
                int c = 2 * ks + ((l >> 3) & 1);
                uint32_t t0r, t1r, t2r, t3r;
                ldsm_x4(t0r, t1r, t2r, t3r, Kc + n * 128 + ((c ^ (n & 7)) << 4));
                bh[j*2][0] = t0r; bh[j*2][1] = t1r; bh[j*2+1][0] = t2r; bh[j*2+1][1] = t3r;
            }
#pragma unroll
            for (int nt = 0; nt < 4; ++nt)
                mma16816h(sacc[nt], aq[ks], bh[nt]);
        }

        // ---- epilogue: p = mask ? exp*inv : 0 -> attn (fp32) + A frags (regs)
        uint32_t pa[2][4];                              // [ksl][a-frag]
#pragma unroll
        for (int h = 0; h < 2; ++h) {
            const int rl = rl0 + h * 8;
            const uint32_t w = g_maskbits[(size_t)(row0 + rl) * 64 + (t0 >> 5) + wn];
            const float inv = sinv[rl];
            float* gp = arow + (size_t)rl * SEQ + t0 + wn * 32 + sh0;
#pragma unroll
            for (int nt = 0; nt < 4; ++nt) {
                const uint32_t bits = w >> (nt * 8 + sh0);
                float p0 = (bits & 1u) ? ex2f(sacc[nt][h * 2 + 0] * LOG2E) * inv : 0.f;
                float p1 = (bits & 2u) ? ex2f(sacc[nt][h * 2 + 1] * LOG2E) * inv : 0.f;
                __stcs((float2*)(gp + nt * 8), make_float2(p0, p1));
                pa[nt >> 1][(nt & 1) * 2 + h] = hpack(p0, p1);
            }
        }

        // ---- PV mma: oacc[all 64 d] += p(16x32) @ v(32x64), K split by wn
        const uint32_t Vc = sb + VT + buf * 8192;
#pragma unroll
        for (int ksl = 0; ksl < 2; ++ksl) {
            const int c = 2 * (wn * 2 + ksl) + ((l >> 3) & 1);
            uint32_t bh[8][2];
#pragma unroll
            for (int j = 0; j < 4; ++j) {
                int n = j * 16 + (l & 7) + ((l >> 4) << 3);
                uint32_t t0r, t1r, t2r, t3r;
                ldsm_x4(t0r, t1r, t2r, t3r, Vc + n * 128 + ((c ^ (n & 7)) << 4));
                bh[j*2][0] = t0r; bh[j*2][1] = t1r; bh[j*2+1][0] = t2r; bh[j*2+1][1] = t3r;
            }
#pragma unroll
            for (int nt2 = 0; nt2 < 8; ++nt2)
                mma16816h(oacc[nt2], pa[ksl], bh[nt2]);
        }
    }

    // ---- pair reduction (wn=1 partial -> smem -> wn=0 adds) + store
    __syncthreads();                                    // KT/VT dead, reuse as RED
    float* red = (float*)(smem + RED);                  // [64][64]
    if (wn == 1) {
#pragma unroll
        for (int nt2 = 0; nt2 < 8; ++nt2) {
            const int gc = nt2 * 8 + sh0;
#pragma unroll
            for (int h = 0; h < 2; ++h) {
                const int rl = rl0 + h * 8;
                *(float2*)(red + rl * 64 + gc) =
                    make_float2(oacc[nt2][h * 2 + 0], oacc[nt2][h * 2 + 1]);
            }
        }
    }
    __syncthreads();
    if (wn == 0) {
#pragma unroll
        for (int nt2 = 0; nt2 < 8; ++nt2) {
            const int gc = nt2 * 8 + sh0;
#pragma unroll
            for (int h = 0; h < 2; ++h) {
                const int rl = rl0 + h * 8;
                float2 o = *(const float2*)(red + rl * 64 + gc);
                *(float2*)(out + ((size_t)(b * SEQ) + row0 + rl) * HD + gc) =
                    make_float2(oacc[nt2][h * 2 + 0] + o.x,
                                oacc[nt2][h * 2 + 1] + o.y);
            }
        }
    }
}

// ===========================================================================
extern "C" void kernel_launch(void* const* d_in, const int* in_sizes, int n_in,
                              void* d_out, int out_size)
{
    const float* q    = (const float*)d_in[0];
    const float* k    = (const float*)d_in[1];
    const float* v    = (const float*)d_in[2];
    const int*   mask = (const int*)d_in[3];

    float* out  = (float*)d_out;
    float* attn = out + (size_t)BATCH * SEQ * HD;

    cudaFuncSetAttribute(scores_mma_kernel,
                         cudaFuncAttributeMaxDynamicSharedMemorySize, 24576);
    cudaFuncSetAttribute(pv_mma_kernel,
                         cudaFuncAttributeMaxDynamicSharedMemorySize, 41216);

    prep_kernel<<<dim3(512, 3), 256>>>((const float4*)q, (const float4*)k, v, mask);

    scores_mma_kernel<<<dim3(32, 16, BATCH), 256, 24576>>>();
    pv_mma_kernel<<<dim3(32, BATCH), 256, 41216>>>(attn, out);
}